// round 12
// baseline (speedup 1.0000x reference)
#include <cuda_runtime.h>
#include <cuda_bf16.h>
#include <cstdint>

#define NVOX 500000
#define KK 27
#define NB_STATS 512

typedef unsigned long long u64;
typedef __nv_bfloat16 bf16;

// ---------------- scratch (__device__ globals; no allocs) ----------------
__device__ __align__(16) bf16  g_h1b[(NVOX + 1) * 64];     // relu(bn1(x)) split [hi32|lo32]
__device__ __align__(16) bf16  g_xb[(NVOX + 1) * 64];      // x split [hi32|lo32]
__device__ __align__(16) float g_h2[(long long)NVOX * 64]; // conv1 out (f32)
__device__ __align__(16) bf16  g_h2b[(NVOX + 1) * 128];    // relu(bn2(h2)) split [hi64|lo64]
__device__ __align__(16) int   g_nbrT[KK * NVOX];          // transposed kernel map
__device__ __align__(16) bf16  g_W1Tb[27 * 64 * 64];       // [k][cout][hi32|lo32]
__device__ __align__(16) bf16  g_W2Tb[54 * 64 * 64];       // [k*2+g][cout][hi32|lo32]
__device__ __align__(16) bf16  g_WresTb[64 * 64];          // [cout][hi32|lo32]
__device__ __align__(16) float g_part[NB_STATS * 64 * 2];
__device__ float g_ab1[64];    // A|B for bn1 (C=32)
__device__ float g_ab2[128];   // A|B for bn2 (C=64)

// ---------------- PTX helpers (all portable, no sm_103a-only features) ----------------
__device__ __forceinline__ uint32_t smem_u32(const void* p) {
    uint32_t a;
    asm("{ .reg .u64 t; cvta.to.shared.u64 t, %1; cvt.u32.u64 %0, t; }" : "=r"(a) : "l"(p));
    return a;
}
#define SW128(o) ((o) ^ (((o) >> 3) & 0x70))

#define CP16CG(d, s) asm volatile("cp.async.cg.shared.global [%0], [%1], 16;" :: "r"(d), "l"(s) : "memory")
#define CP16CA(d, s) asm volatile("cp.async.ca.shared.global [%0], [%1], 16;" :: "r"(d), "l"(s) : "memory")
#define CP_COMMIT()  asm volatile("cp.async.commit_group;" ::: "memory")
#define CP_WAIT1()   asm volatile("cp.async.wait_group 1;" ::: "memory")
#define CP_WAIT0()   asm volatile("cp.async.wait_group 0;" ::: "memory")

__device__ __forceinline__ void ldmx4(uint32_t* r, uint32_t addr) {
    asm volatile("ldmatrix.sync.aligned.m8n8.x4.shared.b16 {%0,%1,%2,%3}, [%4];"
                 : "=r"(r[0]), "=r"(r[1]), "=r"(r[2]), "=r"(r[3]) : "r"(addr));
}
__device__ __forceinline__ void ldmx2(uint32_t* r, uint32_t addr) {
    asm volatile("ldmatrix.sync.aligned.m8n8.x2.shared.b16 {%0,%1}, [%2];"
                 : "=r"(r[0]), "=r"(r[1]) : "r"(addr));
}
__device__ __forceinline__ void mma16816(float* c, const uint32_t* a, const uint32_t* b) {
    asm volatile(
        "mma.sync.aligned.m16n8k16.row.col.f32.bf16.bf16.f32 "
        "{%0,%1,%2,%3}, {%4,%5,%6,%7}, {%8,%9}, {%0,%1,%2,%3};"
        : "+f"(c[0]), "+f"(c[1]), "+f"(c[2]), "+f"(c[3])
        : "r"(a[0]), "r"(a[1]), "r"(a[2]), "r"(a[3]), "r"(b[0]), "r"(b[1]));
}

__device__ __forceinline__ void bsplit(float x, bf16& h, bf16& l) {
    h = __float2bfloat16(x);
    l = __float2bfloat16(x - __bfloat162float(h));
}

// ---------------- prep kernels ----------------
__global__ void prep_weights_kernel(const float* __restrict__ W1,
                                    const float* __restrict__ W2,
                                    const float* __restrict__ Wres) {
    int t = blockIdx.x * blockDim.x + threadIdx.x;
    if (t < 27 * 64 * 32) {  // W1 [27][32][64] -> [k][n][hi c|lo c]
        int k = t / 2048, r = t % 2048, nn = r / 32, c = r % 32;
        float w = W1[(k * 32 + c) * 64 + nn];
        bf16 h, l; bsplit(w, h, l);
        g_W1Tb[(k * 64 + nn) * 64 + c] = h;
        g_W1Tb[(k * 64 + nn) * 64 + 32 + c] = l;
    }
    if (t < 54 * 64 * 32) {  // W2 [27][64][64] -> [k*2+g][n][hi j|lo j]
        int s = t / 2048, r = t % 2048, nn = r / 32, j = r % 32;
        int k = s >> 1, g = s & 1;
        float w = W2[(k * 64 + g * 32 + j) * 64 + nn];
        bf16 h, l; bsplit(w, h, l);
        g_W2Tb[(s * 64 + nn) * 64 + j] = h;
        g_W2Tb[(s * 64 + nn) * 64 + 32 + j] = l;
    }
    if (t < 64 * 32) {  // Wres [32][64] -> [n][hi c|lo c]
        int nn = t / 32, c = t % 32;
        float w = Wres[c * 64 + nn];
        bf16 h, l; bsplit(w, h, l);
        g_WresTb[nn * 64 + c] = h;
        g_WresTb[nn * 64 + 32 + c] = l;
    }
}

__global__ void prep_nbrT_kernel(const int* __restrict__ nbr, int n) {
    int i = blockIdx.x * blockDim.x + threadIdx.x;
    if (i >= n) return;
#pragma unroll
    for (int k = 0; k < KK; ++k) g_nbrT[k * NVOX + i] = nbr[i * KK + k];
}

// ---------------- BN stats (deterministic two-level) ----------------
template <int C>
__global__ void bn_stats_kernel(const float* __restrict__ in_param, int n) {
    const float* __restrict__ in = in_param ? in_param : g_h2;
    constexpr int RL = 256 / C;
    int tid = threadIdx.x, c = tid % C, rl = tid / C;
    float s = 0.f, q = 0.f;
    for (long long r = (long long)blockIdx.x * RL + rl; r < n;
         r += (long long)gridDim.x * RL) {
        float v = in[r * C + c];
        s += v; q += v * v;
    }
    __shared__ float ss[256], sq[256];
    ss[tid] = s; sq[tid] = q;
    __syncthreads();
    for (int step = 128; step >= C; step >>= 1) {
        if (tid < step) { ss[tid] += ss[tid + step]; sq[tid] += sq[tid + step]; }
        __syncthreads();
    }
    if (tid < C) {
        g_part[blockIdx.x * 2 * C + c] = ss[tid];
        g_part[blockIdx.x * 2 * C + C + c] = sq[tid];
    }
}

template <int C>
__global__ void bn_final_kernel(const float* __restrict__ g,
                                const float* __restrict__ b, float invn) {
    int c = threadIdx.x;
    if (c >= C) return;
    float* ab = (C == 32) ? g_ab1 : g_ab2;
    float s = 0.f, q = 0.f;
#pragma unroll 4
    for (int i = 0; i < NB_STATS; i++) {
        s += g_part[i * 2 * C + c];
        q += g_part[i * 2 * C + C + c];
    }
    float m = s * invn;
    float v = q * invn - m * m;
    float A = g[c] * rsqrtf(v + 1e-5f);
    ab[c] = A;
    ab[C + c] = b[c] - m * A;
}

// ---- bn1 apply + relu + split; also split raw x -> g_xb; zero sentinels ----
__global__ void bn_apply1_kernel(const float* __restrict__ x, int n) {
    long long total = (long long)n * 8;
    long long stride = (long long)gridDim.x * blockDim.x;
    for (long long i = (long long)blockIdx.x * blockDim.x + threadIdx.x; i < total; i += stride) {
        long long row = i >> 3;
        int c0 = (int)(i & 7) * 4;
        float4 v = *(const float4*)(x + row * 32 + c0);
        bf16 h, l;
        bf16* xr = g_xb + row * 64;
        bsplit(v.x, h, l); xr[c0 + 0] = h; xr[32 + c0 + 0] = l;
        bsplit(v.y, h, l); xr[c0 + 1] = h; xr[32 + c0 + 1] = l;
        bsplit(v.z, h, l); xr[c0 + 2] = h; xr[32 + c0 + 2] = l;
        bsplit(v.w, h, l); xr[c0 + 3] = h; xr[32 + c0 + 3] = l;
        float4 o;
        o.x = fmaxf(fmaf(v.x, g_ab1[c0 + 0], g_ab1[32 + c0 + 0]), 0.f);
        o.y = fmaxf(fmaf(v.y, g_ab1[c0 + 1], g_ab1[32 + c0 + 1]), 0.f);
        o.z = fmaxf(fmaf(v.z, g_ab1[c0 + 2], g_ab1[32 + c0 + 2]), 0.f);
        o.w = fmaxf(fmaf(v.w, g_ab1[c0 + 3], g_ab1[32 + c0 + 3]), 0.f);
        bf16* hr = g_h1b + row * 64;
        bsplit(o.x, h, l); hr[c0 + 0] = h; hr[32 + c0 + 0] = l;
        bsplit(o.y, h, l); hr[c0 + 1] = h; hr[32 + c0 + 1] = l;
        bsplit(o.z, h, l); hr[c0 + 2] = h; hr[32 + c0 + 2] = l;
        bsplit(o.w, h, l); hr[c0 + 3] = h; hr[32 + c0 + 3] = l;
    }
    long long t = (long long)blockIdx.x * blockDim.x + threadIdx.x;
    if (t < 64) {
        g_h1b[(long long)NVOX * 64 + t] = __float2bfloat16(0.f);
        g_xb[(long long)NVOX * 64 + t] = __float2bfloat16(0.f);
    }
}

// ---- bn2 apply + relu + split: g_h2 (f32) -> g_h2b [hi64|lo64] ----
__global__ void bn_apply2_kernel(int n) {
    long long total = (long long)n * 16;
    long long stride = (long long)gridDim.x * blockDim.x;
    for (long long i = (long long)blockIdx.x * blockDim.x + threadIdx.x; i < total; i += stride) {
        long long row = i >> 4;
        int c0 = (int)(i & 15) * 4;
        float4 v = *(const float4*)(g_h2 + row * 64 + c0);
        float4 o;
        o.x = fmaxf(fmaf(v.x, g_ab2[c0 + 0], g_ab2[64 + c0 + 0]), 0.f);
        o.y = fmaxf(fmaf(v.y, g_ab2[c0 + 1], g_ab2[64 + c0 + 1]), 0.f);
        o.z = fmaxf(fmaf(v.z, g_ab2[c0 + 2], g_ab2[64 + c0 + 2]), 0.f);
        o.w = fmaxf(fmaf(v.w, g_ab2[c0 + 3], g_ab2[64 + c0 + 3]), 0.f);
        bf16 h, l;
        bf16* hr = g_h2b + row * 128;
        bsplit(o.x, h, l); hr[c0 + 0] = h; hr[64 + c0 + 0] = l;
        bsplit(o.y, h, l); hr[c0 + 1] = h; hr[64 + c0 + 1] = l;
        bsplit(o.z, h, l); hr[c0 + 2] = h; hr[64 + c0 + 2] = l;
        bsplit(o.w, h, l); hr[c0 + 3] = h; hr[64 + c0 + 3] = l;
    }
    long long t = (long long)blockIdx.x * blockDim.x + threadIdx.x;
    if (t < 128) g_h2b[(long long)NVOX * 128 + t] = __float2bfloat16(0.f);
}

// ---------------- warp-MMA gather-GEMM sparse conv ----------------
// Block: 128 voxels x 64 cout, 256 threads (8 warps). Warp w owns rows w*16..w*16+15.
// Stage = (k, cin-slab[, residual]). A tile [128 rows][hi32|lo32 bf16] = 16KB SW128,
// B tile [64 n][hi32|lo32] = 8KB SW128, double-buffered via cp.async.
// Per stage per warp: 48 mma.sync m16n8k16 (hh, hl, lh over 2 k-steps x 8 n-tiles).
template <int CONV>
__global__ void __launch_bounds__(256)
conv_mma_kernel(const float* __restrict__ bres, float* __restrict__ out, int n) {
    constexpr int NS = (CONV == 1) ? 27 : 55;
    extern __shared__ __align__(16) char dsm[];

    uint32_t dbase = smem_u32(dsm);
    dbase = (dbase + 1023) & ~1023u;
    const uint32_t Aoff[2] = {dbase, dbase + 16384};
    const uint32_t Boff[2] = {dbase + 32768, dbase + 40960};

    const int tid = threadIdx.x;
    const int lane = tid & 31, w = tid >> 5;
    const long long base = (long long)blockIdx.x * 128;
    const int gvr = tid >> 1, gpart = tid & 1;       // A gather: row, half
    const int brow = tid >> 2, bco = (tid & 3) * 2;  // B gather

    auto load_idx = [&](int s) -> long long {
        long long gv = base + gvr;
        if (CONV == 2 && s >= 54) return (gv < n) ? gv : (long long)n;
        int k = (CONV == 1) ? s : (s >> 1);
        if (gv >= n) return (long long)n;
        return (long long)g_nbrT[(long long)k * NVOX + gv];
    };
    auto issue_gather = [&](int s, int buf, long long idx) {
        const uint32_t Ad = Aoff[buf], Bd = Boff[buf];
        const char* arow;
        int chg = 0;
        bool resid = false;
        if (CONV == 1) {
            arow = (const char*)(g_h1b + idx * 64);
        } else if (s < 54) {
            chg = s & 1;
            arow = (const char*)(g_h2b + idx * 128);
        } else {
            resid = true;
            arow = (const char*)(g_xb + idx * 64);
        }
#pragma unroll
        for (int j = 0; j < 4; ++j) {
            int c = gpart * 4 + j;
            uint32_t doff = (uint32_t)(gvr * 128 + c * 16);
            const char* src;
            if (CONV == 2 && !resid)
                src = (c < 4) ? (arow + chg * 64 + c * 16)
                              : (arow + 128 + chg * 64 + (c - 4) * 16);
            else
                src = arow + c * 16;
            CP16CG(Ad + SW128(doff), src);
        }
        const char* bb;
        if (CONV == 1) bb = (const char*)(g_W1Tb + (long long)s * 4096);
        else bb = resid ? (const char*)g_WresTb : (const char*)(g_W2Tb + (long long)s * 4096);
#pragma unroll
        for (int j = 0; j < 2; ++j) {
            uint32_t doff = (uint32_t)(brow * 128 + (bco + j) * 16);
            CP16CA(Bd + SW128(doff), bb + doff);
        }
    };

    float acc[8][4];
#pragma unroll
    for (int j = 0; j < 8; ++j)
#pragma unroll
        for (int q = 0; q < 4; ++q) acc[j][q] = 0.f;

    // ldmatrix source coordinates
    const int arow_l = w * 16 + (lane & 15);
    const int achk = (lane >> 4) * 16;
    const int brow_l = lane & 7;
    const int bchk = ((lane >> 3) & 1) * 16;

    // ---- pipeline ----
    issue_gather(0, 0, load_idx(0));
    CP_COMMIT();
    long long idxq = (NS > 1) ? load_idx(1) : 0;

    for (int s = 0; s < NS; ++s) {
        const int b = s & 1;
        if (s + 1 < NS) {
            issue_gather(s + 1, (s + 1) & 1, idxq);
            CP_COMMIT();
            if (s + 2 < NS) idxq = load_idx(s + 2);
            CP_WAIT1();
        } else {
            CP_WAIT0();
        }
        __syncthreads();  // buf b visible to all; prior compute joined

        const uint32_t Ab = Aoff[b], Bb = Boff[b];
        uint32_t ah[8], al[8];
#pragma unroll
        for (int kb = 0; kb < 2; ++kb) {
            ldmx4(ah + kb * 4, Ab + SW128((uint32_t)(arow_l * 128 + kb * 32 + achk)));
            ldmx4(al + kb * 4, Ab + SW128((uint32_t)(arow_l * 128 + 64 + kb * 32 + achk)));
        }
#pragma unroll
        for (int j = 0; j < 8; ++j) {
            uint32_t bh[4], bl[4];
#pragma unroll
            for (int kb = 0; kb < 2; ++kb) {
                uint32_t ro = (uint32_t)((j * 8 + brow_l) * 128 + kb * 32 + bchk);
                ldmx2(bh + kb * 2, Bb + SW128(ro));
                ldmx2(bl + kb * 2, Bb + SW128(ro + 64));
            }
#pragma unroll
            for (int kb = 0; kb < 2; ++kb) {
                mma16816(acc[j], ah + kb * 4, bh + kb * 2);  // hi*hi
                mma16816(acc[j], ah + kb * 4, bl + kb * 2);  // hi*lo
                mma16816(acc[j], al + kb * 4, bh + kb * 2);  // lo*hi
            }
        }
        __syncthreads();  // all warps done reading buf b before it is refilled
    }

    // ---- epilogue ----
    const long long r0 = base + w * 16 + (lane >> 2);
    const long long r1 = r0 + 8;
#pragma unroll
    for (int j = 0; j < 8; ++j) {
        int col = j * 8 + (lane & 3) * 2;
        if (CONV == 1) {
            if (r0 < n) *(float2*)(g_h2 + r0 * 64 + col) = make_float2(acc[j][0], acc[j][1]);
            if (r1 < n) *(float2*)(g_h2 + r1 * 64 + col) = make_float2(acc[j][2], acc[j][3]);
        } else {
            float bx = bres[col], by = bres[col + 1];
            if (r0 < n) *(float2*)(out + r0 * 64 + col) = make_float2(acc[j][0] + bx, acc[j][1] + by);
            if (r1 < n) *(float2*)(out + r1 * 64 + col) = make_float2(acc[j][2] + bx, acc[j][3] + by);
        }
    }
}

// ---------------- launch ----------------
extern "C" void kernel_launch(void* const* d_in, const int* in_sizes, int n_in,
                              void* d_out, int out_size) {
    const float* x = (const float*)d_in[0];
    const int* nbr = (const int*)d_in[1];
    const float* W1 = (const float*)d_in[2];
    const float* W2 = (const float*)d_in[3];
    const float* Wres = (const float*)d_in[4];
    const float* bres = (const float*)d_in[5];
    const float* g1 = (const float*)d_in[6];
    const float* b1 = (const float*)d_in[7];
    const float* g2 = (const float*)d_in[8];
    const float* b2 = (const float*)d_in[9];
    float* out = (float*)d_out;

    const int n = NVOX;
    const float invn = 1.0f / (float)n;
    const int conv_grid = (n + 127) / 128;  // 3907
    const int DSM = 50176;

    cudaFuncSetAttribute(conv_mma_kernel<1>, cudaFuncAttributeMaxDynamicSharedMemorySize, DSM);
    cudaFuncSetAttribute(conv_mma_kernel<2>, cudaFuncAttributeMaxDynamicSharedMemorySize, DSM);

    prep_weights_kernel<<<(54 * 64 * 32 + 255) / 256, 256>>>(W1, W2, Wres);
    prep_nbrT_kernel<<<(n + 255) / 256, 256>>>(nbr, n);

    // stage 1: bn1 + relu + split (also split raw x for the residual GEMM)
    bn_stats_kernel<32><<<NB_STATS, 256>>>(x, n);
    bn_final_kernel<32><<<1, 32>>>(g1, b1, invn);
    bn_apply1_kernel<<<2048, 256>>>(x, n);
    // conv1 -> g_h2 (f32)
    conv_mma_kernel<1><<<conv_grid, 256, DSM>>>(nullptr, nullptr, n);
    // stage 2: bn2 + relu + split
    bn_stats_kernel<64><<<NB_STATS, 256>>>(nullptr, n);
    bn_final_kernel<64><<<1, 64>>>(g2, b2, invn);
    bn_apply2_kernel<<<2048, 256>>>(n);
    // conv2 + residual + bres -> out
    conv_mma_kernel<2><<<conv_grid, 256, DSM>>>(bres, out, n);
}

// round 14
// speedup vs baseline: 6.4366x; 6.4366x over previous
#include <cuda_runtime.h>
#include <cstdint>

#define NVOX 500000
#define NB_STATS 512
#define NBLK 1954  // ceil(500000/256)

typedef unsigned long long u64;

// ---------------- scratch ----------------
__device__ __align__(16) float g_h1[(NVOX + 1) * 32];
__device__ __align__(16) float g_h2[(NVOX + 1) * 64];
__device__ __align__(16) int   g_ent[NBLK * 27 * 256];
__device__               int   g_cnt[NBLK * 27];
__device__ __align__(16) float g_part[NB_STATS * 64 * 2];
__device__ float g_ab1[64];
__device__ float g_ab2[128];

// ---------------- helpers ----------------
__device__ __forceinline__ uint32_t smem_u32(const void* p) {
    uint32_t a;
    asm("{ .reg .u64 t; cvta.to.shared.u64 t, %1; cvt.u32.u64 %0, t; }" : "=r"(a) : "l"(p));
    return a;
}
__device__ __forceinline__ void ffma2(u64& d, u64 a, u64 b) {
    asm("fma.rn.f32x2 %0, %1, %2, %3;" : "=l"(d) : "l"(a), "l"(b), "l"(d));
}
__device__ __forceinline__ void unpack2(u64 v, float& x, float& y) {
    asm("mov.b64 {%0, %1}, %2;" : "=f"(x), "=f"(y) : "l"(v));
}
#define CP16(d, s) asm volatile("cp.async.ca.shared.global [%0], [%1], 16;" :: "r"(d), "l"(s) : "memory")
#define CP_COMMIT() asm volatile("cp.async.commit_group;" ::: "memory")
#define CP_WAIT0()  asm volatile("cp.async.wait_group 0;" ::: "memory")

// ---------------- prep: per-(block,offset) compaction ----------------
__global__ void __launch_bounds__(256) prep_compact(const int* __restrict__ nbr, int n) {
    __shared__ int wcnt[8], woff[8];
    const int t = threadIdx.x, wid = t >> 5, lane = t & 31;
    const long long b = blockIdx.x;
    const long long gv = b * 256 + t;
    for (int seg = 0; seg < 27; ++seg) {
        int src = 0; bool valid = false;
        if (gv < n) {
            int sv = nbr[gv * 27 + seg];
            if (sv != n) { src = sv; valid = true; }
        }
        unsigned m = __ballot_sync(0xFFFFFFFFu, valid);
        if (lane == 0) wcnt[wid] = __popc(m);
        __syncthreads();
        if (t == 0) {
            int a = 0;
            for (int w = 0; w < 8; ++w) { woff[w] = a; a += wcnt[w]; }
            g_cnt[b * 27 + seg] = a;
        }
        __syncthreads();
        if (valid) {
            int pos = woff[wid] + __popc(m & ((1u << lane) - 1u));
            g_ent[(b * 27 + seg) * 256 + pos] = src | (t << 20);
        }
        __syncthreads();
    }
}

// ---------------- BN ----------------
template <int C>
__global__ void bn_stats_kernel(const float* __restrict__ in_param, int n) {
    const float* __restrict__ in = in_param ? in_param : g_h2;
    constexpr int RL = 256 / C;
    int tid = threadIdx.x, c = tid % C, rl = tid / C;
    float s = 0.f, q = 0.f;
    for (long long r = (long long)blockIdx.x * RL + rl; r < n; r += (long long)gridDim.x * RL) {
        float v = in[r * C + c];
        s += v; q += v * v;
    }
    __shared__ float ss[256], sq[256];
    ss[tid] = s; sq[tid] = q;
    __syncthreads();
    for (int step = 128; step >= C; step >>= 1) {
        if (tid < step) { ss[tid] += ss[tid + step]; sq[tid] += sq[tid + step]; }
        __syncthreads();
    }
    if (tid < C) {
        g_part[blockIdx.x * 2 * C + c] = ss[tid];
        g_part[blockIdx.x * 2 * C + C + c] = sq[tid];
    }
}

template <int C>
__global__ void bn_final256(const float* __restrict__ g, const float* __restrict__ b, float invn) {
    constexpr int NCH = 256 / C;
    int t = threadIdx.x, c = t % C, ch = t / C;
    float s = 0.f, q = 0.f;
    for (int i = ch; i < NB_STATS; i += NCH) {
        s += g_part[i * 2 * C + c];
        q += g_part[i * 2 * C + C + c];
    }
    __shared__ float ss[256], sq[256];
    ss[t] = s; sq[t] = q;
    __syncthreads();
    for (int step = 128; step >= C; step >>= 1) {
        if (t < step) { ss[t] += ss[t + step]; sq[t] += sq[t + step]; }
        __syncthreads();
    }
    if (t < C) {
        float* ab = (C == 32) ? g_ab1 : g_ab2;
        float m = ss[t] * invn;
        float v = sq[t] * invn - m * m;
        float A = g[c] * rsqrtf(v + 1e-5f);
        ab[c] = A;
        ab[C + c] = b[c] - m * A;
    }
}

__global__ void bn_apply1(const float* __restrict__ x, int n) {
    long long total = (long long)n * 8;
    long long stride = (long long)gridDim.x * blockDim.x;
    for (long long i = (long long)blockIdx.x * blockDim.x + threadIdx.x; i < total; i += stride) {
        int c0 = (int)(i & 7) * 4;
        float4 v = ((const float4*)x)[i];
        float4 o;
        o.x = fmaxf(fmaf(v.x, g_ab1[c0 + 0], g_ab1[32 + c0 + 0]), 0.f);
        o.y = fmaxf(fmaf(v.y, g_ab1[c0 + 1], g_ab1[32 + c0 + 1]), 0.f);
        o.z = fmaxf(fmaf(v.z, g_ab1[c0 + 2], g_ab1[32 + c0 + 2]), 0.f);
        o.w = fmaxf(fmaf(v.w, g_ab1[c0 + 3], g_ab1[32 + c0 + 3]), 0.f);
        ((float4*)g_h1)[i] = o;
    }
}

__global__ void bn_apply2(int n) {  // in place on g_h2
    long long total = (long long)n * 16;
    long long stride = (long long)gridDim.x * blockDim.x;
    for (long long i = (long long)blockIdx.x * blockDim.x + threadIdx.x; i < total; i += stride) {
        int c0 = (int)(i & 15) * 4;
        float4 v = ((const float4*)g_h2)[i];
        float4 o;
        o.x = fmaxf(fmaf(v.x, g_ab2[c0 + 0], g_ab2[64 + c0 + 0]), 0.f);
        o.y = fmaxf(fmaf(v.y, g_ab2[c0 + 1], g_ab2[64 + c0 + 1]), 0.f);
        o.z = fmaxf(fmaf(v.z, g_ab2[c0 + 2], g_ab2[64 + c0 + 2]), 0.f);
        o.w = fmaxf(fmaf(v.w, g_ab2[c0 + 3], g_ab2[64 + c0 + 3]), 0.f);
        ((float4*)g_h2)[i] = o;
    }
}

// ---------------- sparse-compacted conv ----------------
// Block = 256 output voxels, 512 threads. smem: acc[257][68] f32 (row 256 = trash),
// A dup-rows double-buffered (64 entries/sub-batch), W double-buffered via cp.async.
// Thread: entry slot eloc = t>>3, channel group cg = t&7 (channels cg*8..cg*8+7).
template <int CONV>
__global__ void __launch_bounds__(512, 1)
conv_sparse(const float* __restrict__ x, const float* __restrict__ W,
            const float* __restrict__ Wres, const float* __restrict__ bres,
            float* __restrict__ out_p, int n) {
    constexpr int NSEG = (CONV == 1) ? 27 : 28;
    constexpr int CM = (CONV == 1) ? 32 : 64;     // main cin
    constexpr int ASTR = (CONV == 1) ? 68 : 132;  // dup row stride (floats)
    constexpr int WBUF = CM * 64;                 // floats per W buffer
    constexpr int ACCF = 257 * 68;
    constexpr int ASF = 64 * ASTR;
    extern __shared__ __align__(16) float sm[];
    float* accs = sm;
    float* As = sm + ACCF;
    float* Ws = sm + ACCF + 2 * ASF;
    const uint32_t WsA = smem_u32(Ws);

    const int t = threadIdx.x;
    const int eloc = t >> 3, cg = t & 7;
    const long long b = blockIdx.x;
    const long long base = b * 256;
    float* o = (CONV == 1) ? g_h2 : out_p;

    for (int i = t; i < ACCF; i += 512) accs[i] = 0.f;

    // W prefetch for seg 0
    {
        const float* src = W;
        for (int i = t * 16; i < CM * 256; i += 8192) CP16(WsA + i, (const char*)src + i);
        CP_COMMIT();
    }

    for (int s = 0; s < NSEG; ++s) {
        CP_WAIT0();
        __syncthreads();  // W(s) visible; prior compute done
        if (s + 1 < NSEG) {
            const bool nres = (CONV == 2 && s + 1 == 27);
            const float* src = nres ? Wres : (W + (s + 1) * WBUF);
            const int nb = nres ? 8192 : CM * 256;
            const uint32_t dA = WsA + ((s + 1) & 1) * WBUF * 4;
            for (int i = t * 16; i < nb; i += 8192) CP16(dA + i, (const char*)src + i);
            CP_COMMIT();
        }
        const bool resid = (CONV == 2 && s == 27);
        const int cnt = resid ? (int)((base + 256 <= n) ? 256 : (n - base))
                              : g_cnt[b * 27 + s];
        const int nsb = (cnt + 63) >> 6;
        if (nsb == 0) continue;
        const int cin = resid ? 32 : CM;
        const float* Wseg = Ws + (s & 1) * WBUF;
        const int nch = (CONV == 1 || resid) ? 1 : 2;  // f4 chunks per thread

        // gather helper (into regs)
        float4 f[2]; int lv_c;
        auto ldg = [&](int sb, float4* ff, int& lv) {
            int e = sb * 64 + eloc;
            bool valid = false; int src_i = 0;
            if (resid) {
                if (e < cnt) { valid = true; src_i = (int)(base + e); lv = e; } else lv = 256;
            } else {
                if (e < cnt) {
                    int ent = g_ent[(b * 27 + s) * 256 + e];
                    src_i = ent & 0xFFFFF; lv = ent >> 20; valid = true;
                } else lv = 256;
            }
            const float4* f4 = resid ? (const float4*)x
                              : (CONV == 1 ? (const float4*)g_h1 : (const float4*)g_h2);
            const int rowf4 = (CONV == 1 || resid) ? 8 : 16;
            for (int jj = 0; jj < nch; ++jj) {
                int j = cg + jj * 8;
                ff[jj] = valid ? f4[(long long)src_i * rowf4 + j] : make_float4(0.f, 0.f, 0.f, 0.f);
            }
        };
        auto sts = [&](int buf, const float4* ff) {
            float* row = As + buf * ASF + eloc * ASTR;
            for (int jj = 0; jj < nch; ++jj) {
                int j = cg + jj * 8;
                float4 v = ff[jj];
                *(float4*)(row + 8 * j) = make_float4(v.x, v.x, v.y, v.y);
                *(float4*)(row + 8 * j + 4) = make_float4(v.z, v.z, v.w, v.w);
            }
        };

        ldg(0, f, lv_c);
        sts(0, f);
        __syncthreads();

        for (int sb = 0; sb < nsb; ++sb) {
            float4 fn[2]; int lv_n = 256;
            if (sb + 1 < nsb) ldg(sb + 1, fn, lv_n);
            // compute sub-batch sb from buffer sb&1
            {
                const u64* arow = (const u64*)(As + (sb & 1) * ASF + eloc * ASTR);
                u64 acc0 = 0, acc1 = 0, acc2 = 0, acc3 = 0;
                const int c2max = cin >> 1;
#pragma unroll 8
                for (int c2 = 0; c2 < c2max; ++c2) {
                    ulonglong2 av = *(const ulonglong2*)(arow + c2 * 2);
                    const float* wc0 = Wseg + (2 * c2) * 64 + cg * 8;
                    ulonglong2 w0a = *(const ulonglong2*)(wc0);
                    ulonglong2 w0b = *(const ulonglong2*)(wc0 + 4);
                    ulonglong2 w1a = *(const ulonglong2*)(wc0 + 64);
                    ulonglong2 w1b = *(const ulonglong2*)(wc0 + 68);
                    ffma2(acc0, av.x, w0a.x); ffma2(acc1, av.x, w0a.y);
                    ffma2(acc2, av.x, w0b.x); ffma2(acc3, av.x, w0b.y);
                    ffma2(acc0, av.y, w1a.x); ffma2(acc1, av.y, w1a.y);
                    ffma2(acc2, av.y, w1b.x); ffma2(acc3, av.y, w1b.y);
                }
                float2* ap = (float2*)(accs + lv_c * 68 + cg * 8);
                float lo, hi; float2 v;
                unpack2(acc0, lo, hi); v = ap[0]; ap[0] = make_float2(v.x + lo, v.y + hi);
                unpack2(acc1, lo, hi); v = ap[1]; ap[1] = make_float2(v.x + lo, v.y + hi);
                unpack2(acc2, lo, hi); v = ap[2]; ap[2] = make_float2(v.x + lo, v.y + hi);
                unpack2(acc3, lo, hi); v = ap[3]; ap[3] = make_float2(v.x + lo, v.y + hi);
            }
            if (sb + 1 < nsb) {
                sts((sb + 1) & 1, fn);  // safe: buffer last read in sub-batch sb-1 (synced)
                __syncthreads();
                lv_c = lv_n;
            }
        }
    }
    __syncthreads();

    // writeout: thread -> (row r = t>>1, half = t&1)
    {
        const int r = t >> 1, half = t & 1;
        const long long gv = base + r;
        if (gv < n) {
            const float4* asrc = (const float4*)(accs + r * 68 + half * 32);
            float4* od = (float4*)(o + gv * 64 + half * 32);
#pragma unroll
            for (int j = 0; j < 8; ++j) {
                float4 v = asrc[j];
                if (CONV == 2) {
                    float4 bb = ((const float4*)bres)[half * 8 + j];
                    v.x += bb.x; v.y += bb.y; v.z += bb.z; v.w += bb.w;
                }
                od[j] = v;
            }
        }
    }
}

// ---------------- launch ----------------
extern "C" void kernel_launch(void* const* d_in, const int* in_sizes, int n_in,
                              void* d_out, int out_size) {
    const float* x = (const float*)d_in[0];
    const int* nbr = (const int*)d_in[1];
    const float* W1 = (const float*)d_in[2];
    const float* W2 = (const float*)d_in[3];
    const float* Wres = (const float*)d_in[4];
    const float* bres = (const float*)d_in[5];
    const float* g1 = (const float*)d_in[6];
    const float* b1 = (const float*)d_in[7];
    const float* g2 = (const float*)d_in[8];
    const float* b2 = (const float*)d_in[9];
    float* out = (float*)d_out;

    const int n = NVOX;
    const float invn = 1.0f / (float)n;
    const int SM1 = (257 * 68 + 2 * 64 * 68 + 2 * 2048) * 4;   // 121,104 B
    const int SM2 = (257 * 68 + 2 * 64 * 132 + 2 * 4096) * 4;  // 170,256 B

    cudaFuncSetAttribute(conv_sparse<1>, cudaFuncAttributeMaxDynamicSharedMemorySize, SM1);
    cudaFuncSetAttribute(conv_sparse<2>, cudaFuncAttributeMaxDynamicSharedMemorySize, SM2);

    prep_compact<<<NBLK, 256>>>(nbr, n);
    bn_stats_kernel<32><<<NB_STATS, 256>>>(x, n);
    bn_final256<32><<<1, 256>>>(g1, b1, invn);
    bn_apply1<<<2048, 256>>>(x, n);
    conv_sparse<1><<<NBLK, 512, SM1>>>(x, W1, Wres, bres, nullptr, n);
    bn_stats_kernel<64><<<NB_STATS, 256>>>(nullptr, n);
    bn_final256<64><<<1, 256>>>(g2, b2, invn);
    bn_apply2<<<2048, 256>>>(n);
    conv_sparse<2><<<NBLK, 512, SM2>>>(x, W2, Wres, bres, out, n);
}

// round 16
// speedup vs baseline: 6.7573x; 1.0498x over previous
#include <cuda_runtime.h>
#include <cstdint>

#define NVOX 500000
#define NB_STATS 512
#define NBLK 1954  // ceil(500000/256)

typedef unsigned long long u64;

// ---------------- scratch ----------------
__device__ __align__(16) float g_h1[(NVOX + 1) * 32];
__device__ __align__(16) float g_h2[(NVOX + 1) * 64];
__device__ __align__(16) int   g_ent[NBLK * 27 * 256];
__device__               int   g_cnt[NBLK * 27];
__device__ __align__(16) float g_part[NB_STATS * 64 * 2];
__device__ float g_ab1[64];
__device__ float g_ab2[128];

// ---------------- helpers ----------------
__device__ __forceinline__ uint32_t smem_u32(const void* p) {
    uint32_t a;
    asm("{ .reg .u64 t; cvta.to.shared.u64 t, %1; cvt.u32.u64 %0, t; }" : "=r"(a) : "l"(p));
    return a;
}
__device__ __forceinline__ void ffma2(u64& d, u64 a, u64 b) {
    asm("fma.rn.f32x2 %0, %1, %2, %3;" : "=l"(d) : "l"(a), "l"(b), "l"(d));
}
__device__ __forceinline__ void unpack2(u64 v, float& x, float& y) {
    asm("mov.b64 {%0, %1}, %2;" : "=f"(x), "=f"(y) : "l"(v));
}
#define CP16(d, s) asm volatile("cp.async.ca.shared.global [%0], [%1], 16;" :: "r"(d), "l"(s) : "memory")
#define CP_COMMIT() asm volatile("cp.async.commit_group;" ::: "memory")
#define CP_WAIT0()  asm volatile("cp.async.wait_group 0;" ::: "memory")

// ---------------- prep: per-(block,offset) compaction ----------------
__global__ void __launch_bounds__(256) prep_compact(const int* __restrict__ nbr, int n) {
    __shared__ int wcnt[8], woff[8];
    const int t = threadIdx.x, wid = t >> 5, lane = t & 31;
    const long long b = blockIdx.x;
    const long long gv = b * 256 + t;
    for (int seg = 0; seg < 27; ++seg) {
        int src = 0; bool valid = false;
        if (gv < n) {
            int sv = nbr[gv * 27 + seg];
            if (sv != n) { src = sv; valid = true; }
        }
        unsigned m = __ballot_sync(0xFFFFFFFFu, valid);
        if (lane == 0) wcnt[wid] = __popc(m);
        __syncthreads();
        if (t == 0) {
            int a = 0;
            for (int w = 0; w < 8; ++w) { woff[w] = a; a += wcnt[w]; }
            g_cnt[b * 27 + seg] = a;
        }
        __syncthreads();
        if (valid) {
            int pos = woff[wid] + __popc(m & ((1u << lane) - 1u));
            g_ent[(b * 27 + seg) * 256 + pos] = src | (t << 20);
        }
        __syncthreads();
    }
}

// ---------------- BN ----------------
template <int C>
__global__ void bn_stats_kernel(const float* __restrict__ in_param, int n) {
    const float* __restrict__ in = in_param ? in_param : g_h2;
    constexpr int RL = 256 / C;
    int tid = threadIdx.x, c = tid % C, rl = tid / C;
    float s = 0.f, q = 0.f;
    for (long long r = (long long)blockIdx.x * RL + rl; r < n; r += (long long)gridDim.x * RL) {
        float v = in[r * C + c];
        s += v; q += v * v;
    }
    __shared__ float ss[256], sq[256];
    ss[tid] = s; sq[tid] = q;
    __syncthreads();
    for (int step = 128; step >= C; step >>= 1) {
        if (tid < step) { ss[tid] += ss[tid + step]; sq[tid] += sq[tid + step]; }
        __syncthreads();
    }
    if (tid < C) {
        g_part[blockIdx.x * 2 * C + c] = ss[tid];
        g_part[blockIdx.x * 2 * C + C + c] = sq[tid];
    }
}

template <int C>
__global__ void bn_final256(const float* __restrict__ g, const float* __restrict__ b, float invn) {
    constexpr int NCH = 256 / C;
    int t = threadIdx.x, c = t % C, ch = t / C;
    float s = 0.f, q = 0.f;
    for (int i = ch; i < NB_STATS; i += NCH) {
        s += g_part[i * 2 * C + c];
        q += g_part[i * 2 * C + C + c];
    }
    __shared__ float ss[256], sq[256];
    ss[t] = s; sq[t] = q;
    __syncthreads();
    for (int step = 128; step >= C; step >>= 1) {
        if (t < step) { ss[t] += ss[t + step]; sq[t] += sq[t + step]; }
        __syncthreads();
    }
    if (t < C) {
        float* ab = (C == 32) ? g_ab1 : g_ab2;
        float m = ss[t] * invn;
        float v = sq[t] * invn - m * m;
        float A = g[c] * rsqrtf(v + 1e-5f);
        ab[c] = A;
        ab[C + c] = b[c] - m * A;
    }
}

__global__ void bn_apply1(const float* __restrict__ x, int n) {
    long long total = (long long)n * 8;
    long long stride = (long long)gridDim.x * blockDim.x;
    for (long long i = (long long)blockIdx.x * blockDim.x + threadIdx.x; i < total; i += stride) {
        int c0 = (int)(i & 7) * 4;
        float4 v = ((const float4*)x)[i];
        float4 o;
        o.x = fmaxf(fmaf(v.x, g_ab1[c0 + 0], g_ab1[32 + c0 + 0]), 0.f);
        o.y = fmaxf(fmaf(v.y, g_ab1[c0 + 1], g_ab1[32 + c0 + 1]), 0.f);
        o.z = fmaxf(fmaf(v.z, g_ab1[c0 + 2], g_ab1[32 + c0 + 2]), 0.f);
        o.w = fmaxf(fmaf(v.w, g_ab1[c0 + 3], g_ab1[32 + c0 + 3]), 0.f);
        ((float4*)g_h1)[i] = o;
    }
}

__global__ void bn_apply2(int n) {  // in place on g_h2
    long long total = (long long)n * 16;
    long long stride = (long long)gridDim.x * blockDim.x;
    for (long long i = (long long)blockIdx.x * blockDim.x + threadIdx.x; i < total; i += stride) {
        int c0 = (int)(i & 15) * 4;
        float4 v = ((const float4*)g_h2)[i];
        float4 o;
        o.x = fmaxf(fmaf(v.x, g_ab2[c0 + 0], g_ab2[64 + c0 + 0]), 0.f);
        o.y = fmaxf(fmaf(v.y, g_ab2[c0 + 1], g_ab2[64 + c0 + 1]), 0.f);
        o.z = fmaxf(fmaf(v.z, g_ab2[c0 + 2], g_ab2[64 + c0 + 2]), 0.f);
        o.w = fmaxf(fmaf(v.w, g_ab2[c0 + 3], g_ab2[64 + c0 + 3]), 0.f);
        ((float4*)g_h2)[i] = o;
    }
}

// ---------------- sparse-compacted conv ----------------
// Block = 256 output voxels, 512 threads. smem: acc[257][68] f32 (row 256 = trash),
// A dup-rows double-buffered (64 entries/sub-batch), W double-buffered via cp.async.
// Thread: entry slot eloc = t>>3, channel group cg = t&7 (channels cg*8..cg*8+7).
template <int CONV>
__global__ void __launch_bounds__(512, 1)
conv_sparse(const float* __restrict__ x, const float* __restrict__ W,
            const float* __restrict__ Wres, const float* __restrict__ bres,
            float* __restrict__ out_p, int n) {
    constexpr int NSEG = (CONV == 1) ? 27 : 28;
    constexpr int CM = (CONV == 1) ? 32 : 64;     // main cin
    constexpr int ASTR = (CONV == 1) ? 68 : 132;  // dup row stride (floats)
    constexpr int WBUF = CM * 64;                 // floats per W buffer
    constexpr int ACCF = 257 * 68;
    constexpr int ASF = 64 * ASTR;
    extern __shared__ __align__(16) float sm[];
    float* accs = sm;
    float* As = sm + ACCF;
    float* Ws = sm + ACCF + 2 * ASF;
    const uint32_t WsA = smem_u32(Ws);

    const int t = threadIdx.x;
    const int eloc = t >> 3, cg = t & 7;
    const long long b = blockIdx.x;
    const long long base = b * 256;
    float* o = (CONV == 1) ? g_h2 : out_p;

    for (int i = t; i < ACCF; i += 512) accs[i] = 0.f;

    // W prefetch for seg 0
    {
        const float* src = W;
        for (int i = t * 16; i < CM * 256; i += 8192) CP16(WsA + i, (const char*)src + i);
        CP_COMMIT();
    }

    for (int s = 0; s < NSEG; ++s) {
        CP_WAIT0();
        __syncthreads();  // W(s) visible; prior compute done
        if (s + 1 < NSEG) {
            const bool nres = (CONV == 2 && s + 1 == 27);
            const float* src = nres ? Wres : (W + (s + 1) * WBUF);
            const int nb = nres ? 8192 : CM * 256;
            const uint32_t dA = WsA + ((s + 1) & 1) * WBUF * 4;
            for (int i = t * 16; i < nb; i += 8192) CP16(dA + i, (const char*)src + i);
            CP_COMMIT();
        }
        const bool resid = (CONV == 2 && s == 27);
        const int cnt = resid ? (int)((base + 256 <= n) ? 256 : (n - base))
                              : g_cnt[b * 27 + s];
        const int nsb = (cnt + 63) >> 6;
        if (nsb == 0) continue;
        const int cin = resid ? 32 : CM;
        const float* Wseg = Ws + (s & 1) * WBUF;
        const int nch = (CONV == 1 || resid) ? 1 : 2;  // f4 chunks per thread

        // gather helper (into regs)
        float4 f[2]; int lv_c;
        auto ldg = [&](int sb, float4* ff, int& lv) {
            int e = sb * 64 + eloc;
            bool valid = false; int src_i = 0;
            if (resid) {
                if (e < cnt) { valid = true; src_i = (int)(base + e); lv = e; } else lv = 256;
            } else {
                if (e < cnt) {
                    int ent = g_ent[(b * 27 + s) * 256 + e];
                    src_i = ent & 0xFFFFF; lv = ent >> 20; valid = true;
                } else lv = 256;
            }
            const float4* f4 = resid ? (const float4*)x
                              : (CONV == 1 ? (const float4*)g_h1 : (const float4*)g_h2);
            const int rowf4 = (CONV == 1 || resid) ? 8 : 16;
            for (int jj = 0; jj < nch; ++jj) {
                int j = cg + jj * 8;
                ff[jj] = valid ? f4[(long long)src_i * rowf4 + j] : make_float4(0.f, 0.f, 0.f, 0.f);
            }
        };
        auto sts = [&](int buf, const float4* ff) {
            float* row = As + buf * ASF + eloc * ASTR;
            for (int jj = 0; jj < nch; ++jj) {
                int j = cg + jj * 8;
                float4 v = ff[jj];
                *(float4*)(row + 8 * j) = make_float4(v.x, v.x, v.y, v.y);
                *(float4*)(row + 8 * j + 4) = make_float4(v.z, v.z, v.w, v.w);
            }
        };

        ldg(0, f, lv_c);
        sts(0, f);
        __syncthreads();

        for (int sb = 0; sb < nsb; ++sb) {
            float4 fn[2]; int lv_n = 256;
            if (sb + 1 < nsb) ldg(sb + 1, fn, lv_n);
            // compute sub-batch sb from buffer sb&1
            {
                const u64* arow = (const u64*)(As + (sb & 1) * ASF + eloc * ASTR);
                u64 acc0 = 0, acc1 = 0, acc2 = 0, acc3 = 0;
                const int c2max = cin >> 1;
#pragma unroll 8
                for (int c2 = 0; c2 < c2max; ++c2) {
                    ulonglong2 av = *(const ulonglong2*)(arow + c2 * 2);
                    const float* wc0 = Wseg + (2 * c2) * 64 + cg * 8;
                    ulonglong2 w0a = *(const ulonglong2*)(wc0);
                    ulonglong2 w0b = *(const ulonglong2*)(wc0 + 4);
                    ulonglong2 w1a = *(const ulonglong2*)(wc0 + 64);
                    ulonglong2 w1b = *(const ulonglong2*)(wc0 + 68);
                    ffma2(acc0, av.x, w0a.x); ffma2(acc1, av.x, w0a.y);
                    ffma2(acc2, av.x, w0b.x); ffma2(acc3, av.x, w0b.y);
                    ffma2(acc0, av.y, w1a.x); ffma2(acc1, av.y, w1a.y);
                    ffma2(acc2, av.y, w1b.x); ffma2(acc3, av.y, w1b.y);
                }
                float2* ap = (float2*)(accs + lv_c * 68 + cg * 8);
                float lo, hi; float2 v;
                unpack2(acc0, lo, hi); v = ap[0]; ap[0] = make_float2(v.x + lo, v.y + hi);
                unpack2(acc1, lo, hi); v = ap[1]; ap[1] = make_float2(v.x + lo, v.y + hi);
                unpack2(acc2, lo, hi); v = ap[2]; ap[2] = make_float2(v.x + lo, v.y + hi);
                unpack2(acc3, lo, hi); v = ap[3]; ap[3] = make_float2(v.x + lo, v.y + hi);
            }
            if (sb + 1 < nsb) {
                sts((sb + 1) & 1, fn);  // safe: buffer last read in sub-batch sb-1 (synced)
                __syncthreads();
                lv_c = lv_n;
            }
        }
    }
    __syncthreads();

    // writeout: thread -> (row r = t>>1, half = t&1)
    {
        const int r = t >> 1, half = t & 1;
        const long long gv = base + r;
        if (gv < n) {
            const float4* asrc = (const float4*)(accs + r * 68 + half * 32);
            float4* od = (float4*)(o + gv * 64 + half * 32);
#pragma unroll
            for (int j = 0; j < 8; ++j) {
                float4 v = asrc[j];
                if (CONV == 2) {
                    float4 bb = ((const float4*)bres)[half * 8 + j];
                    v.x += bb.x; v.y += bb.y; v.z += bb.z; v.w += bb.w;
                }
                od[j] = v;
            }
        }
    }
}

// ---------------- launch ----------------
extern "C" void kernel_launch(void* const* d_in, const int* in_sizes, int n_in,
                              void* d_out, int out_size) {
    const float* x = (const float*)d_in[0];
    const int* nbr = (const int*)d_in[1];
    const float* W1 = (const float*)d_in[2];
    const float* W2 = (const float*)d_in[3];
    const float* Wres = (const float*)d_in[4];
    const float* bres = (const float*)d_in[5];
    const float* g1 = (const float*)d_in[6];
    const float* b1 = (const float*)d_in[7];
    const float* g2 = (const float*)d_in[8];
    const float* b2 = (const float*)d_in[9];
    float* out = (float*)d_out;

    const int n = NVOX;
    const float invn = 1.0f / (float)n;
    const int SM1 = (257 * 68 + 2 * 64 * 68 + 2 * 2048) * 4;   // 121,104 B
    const int SM2 = (257 * 68 + 2 * 64 * 132 + 2 * 4096) * 4;  // 170,256 B

    cudaFuncSetAttribute(conv_sparse<1>, cudaFuncAttributeMaxDynamicSharedMemorySize, SM1);
    cudaFuncSetAttribute(conv_sparse<2>, cudaFuncAttributeMaxDynamicSharedMemorySize, SM2);

    prep_compact<<<NBLK, 256>>>(nbr, n);
    bn_stats_kernel<32><<<NB_STATS, 256>>>(x, n);
    bn_final256<32><<<1, 256>>>(g1, b1, invn);
    bn_apply1<<<2048, 256>>>(x, n);
    conv_sparse<1><<<NBLK, 512, SM1>>>(x, W1, Wres, bres, nullptr, n);
    bn_stats_kernel<64><<<NB_STATS, 256>>>(nullptr, n);
    bn_final256<64><<<1, 256>>>(g2, b2, invn);
    bn_apply2<<<2048, 256>>>(n);
    conv_sparse<2><<<NBLK, 512, SM2>>>(x, W2, Wres, bres, out, n);
}

// round 17
// speedup vs baseline: 27.0291x; 4.0000x over previous
#include <cuda_runtime.h>
#include <cstdint>

#define NVOX 500000
#define NB_STATS 512
#define NBLK 977  // ceil(500000/512)

typedef unsigned long long u64;

// ---------------- scratch ----------------
__device__ __align__(16) float g_h1[(NVOX + 1) * 32];
__device__ __align__(16) float g_h2[(NVOX + 1) * 64];
__device__ __align__(16) int   g_ent[(long long)NBLK * 27 * 512];
__device__               int   g_cnt[NBLK * 27];
__device__ __align__(16) float g_part[NB_STATS * 64 * 2];
__device__ float g_ab1[64];
__device__ float g_ab2[128];

// ---------------- helpers ----------------
__device__ __forceinline__ uint32_t smem_u32(const void* p) {
    uint32_t a;
    asm("{ .reg .u64 t; cvta.to.shared.u64 t, %1; cvt.u32.u64 %0, t; }" : "=r"(a) : "l"(p));
    return a;
}
__device__ __forceinline__ u64 pack2(float x, float y) {
    u64 r; asm("mov.b64 %0, {%1, %2};" : "=l"(r) : "f"(x), "f"(y)); return r;
}
__device__ __forceinline__ void unpack2(u64 v, float& x, float& y) {
    asm("mov.b64 {%0, %1}, %2;" : "=f"(x), "=f"(y) : "l"(v));
}
__device__ __forceinline__ void ffma2(u64& d, u64 a, u64 b) {
    asm("fma.rn.f32x2 %0, %1, %2, %3;" : "=l"(d) : "l"(a), "l"(b), "l"(d));
}
#define CP16(d, s) asm volatile("cp.async.ca.shared.global [%0], [%1], 16;" :: "r"(d), "l"(s) : "memory")
#define CP_COMMIT() asm volatile("cp.async.commit_group;" ::: "memory")
#define CP_WAIT0()  asm volatile("cp.async.wait_group 0;" ::: "memory")

// ---------------- prep: per-(block,offset) compaction ----------------
__global__ void __launch_bounds__(512) prep_compact(const int* __restrict__ nbr, int n) {
    __shared__ int wcnt[16], woff[16];
    const int t = threadIdx.x, wid = t >> 5, lane = t & 31;
    const long long b = blockIdx.x;
    const long long gv = b * 512 + t;
    int nb[27];
    if (gv < n) {
#pragma unroll
        for (int k = 0; k < 27; ++k) nb[k] = nbr[gv * 27 + k];
    } else {
#pragma unroll
        for (int k = 0; k < 27; ++k) nb[k] = n;
    }
    for (int seg = 0; seg < 27; ++seg) {
        int sv = nb[seg];
        bool valid = (sv != n);
        unsigned m = __ballot_sync(0xFFFFFFFFu, valid);
        if (lane == 0) wcnt[wid] = __popc(m);
        __syncthreads();
        if (t == 0) {
            int a = 0;
            for (int w = 0; w < 16; ++w) { woff[w] = a; a += wcnt[w]; }
            g_cnt[b * 27 + seg] = a;
        }
        __syncthreads();
        if (valid) {
            int pos = woff[wid] + __popc(m & ((1u << lane) - 1u));
            g_ent[((long long)b * 27 + seg) * 512 + pos] = sv | (t << 20);
        }
        __syncthreads();
    }
}

// ---------------- BN ----------------
template <int C>
__global__ void bn_stats_kernel(const float* __restrict__ in_param, int n) {
    const float* __restrict__ in = in_param ? in_param : g_h2;
    constexpr int RL = 256 / C;
    int tid = threadIdx.x, c = tid % C, rl = tid / C;
    float s = 0.f, q = 0.f;
    for (long long r = (long long)blockIdx.x * RL + rl; r < n; r += (long long)gridDim.x * RL) {
        float v = in[r * C + c];
        s += v; q += v * v;
    }
    __shared__ float ss[256], sq[256];
    ss[tid] = s; sq[tid] = q;
    __syncthreads();
    for (int step = 128; step >= C; step >>= 1) {
        if (tid < step) { ss[tid] += ss[tid + step]; sq[tid] += sq[tid + step]; }
        __syncthreads();
    }
    if (tid < C) {
        g_part[blockIdx.x * 2 * C + c] = ss[tid];
        g_part[blockIdx.x * 2 * C + C + c] = sq[tid];
    }
}

template <int C>
__global__ void bn_final256(const float* __restrict__ g, const float* __restrict__ b, float invn) {
    constexpr int NCH = 256 / C;
    int t = threadIdx.x, c = t % C, ch = t / C;
    float s = 0.f, q = 0.f;
    for (int i = ch; i < NB_STATS; i += NCH) {
        s += g_part[i * 2 * C + c];
        q += g_part[i * 2 * C + C + c];
    }
    __shared__ float ss[256], sq[256];
    ss[t] = s; sq[t] = q;
    __syncthreads();
    for (int step = 128; step >= C; step >>= 1) {
        if (t < step) { ss[t] += ss[t + step]; sq[t] += sq[t + step]; }
        __syncthreads();
    }
    if (t < C) {
        float* ab = (C == 32) ? g_ab1 : g_ab2;
        float m = ss[t] * invn;
        float v = sq[t] * invn - m * m;
        float A = g[c] * rsqrtf(v + 1e-5f);
        ab[c] = A;
        ab[C + c] = b[c] - m * A;
    }
}

__global__ void bn_apply1(const float* __restrict__ x, int n) {
    long long total = (long long)n * 8;
    long long stride = (long long)gridDim.x * blockDim.x;
    for (long long i = (long long)blockIdx.x * blockDim.x + threadIdx.x; i < total; i += stride) {
        int c0 = (int)(i & 7) * 4;
        float4 v = ((const float4*)x)[i];
        float4 o;
        o.x = fmaxf(fmaf(v.x, g_ab1[c0 + 0], g_ab1[32 + c0 + 0]), 0.f);
        o.y = fmaxf(fmaf(v.y, g_ab1[c0 + 1], g_ab1[32 + c0 + 1]), 0.f);
        o.z = fmaxf(fmaf(v.z, g_ab1[c0 + 2], g_ab1[32 + c0 + 2]), 0.f);
        o.w = fmaxf(fmaf(v.w, g_ab1[c0 + 3], g_ab1[32 + c0 + 3]), 0.f);
        ((float4*)g_h1)[i] = o;
    }
}

__global__ void bn_apply2(int n) {  // in place on g_h2
    long long total = (long long)n * 16;
    long long stride = (long long)gridDim.x * blockDim.x;
    for (long long i = (long long)blockIdx.x * blockDim.x + threadIdx.x; i < total; i += stride) {
        int c0 = (int)(i & 15) * 4;
        float4 v = ((const float4*)g_h2)[i];
        float4 o;
        o.x = fmaxf(fmaf(v.x, g_ab2[c0 + 0], g_ab2[64 + c0 + 0]), 0.f);
        o.y = fmaxf(fmaf(v.y, g_ab2[c0 + 1], g_ab2[64 + c0 + 1]), 0.f);
        o.z = fmaxf(fmaf(v.z, g_ab2[c0 + 2], g_ab2[64 + c0 + 2]), 0.f);
        o.w = fmaxf(fmaf(v.w, g_ab2[c0 + 3], g_ab2[64 + c0 + 3]), 0.f);
        ((float4*)g_h2)[i] = o;
    }
}

// ---------------- sparse conv: dense tile engine over compacted entries ----------------
// Block = 512 outputs. 256 threads. Pass = 128 entries x 64 couts x cin (R5 engine).
// Segment order: center(13, store-mode) first, then RMW segs, then residual (conv2).
template <int CONV>
__global__ void __launch_bounds__(256)
conv_pass(const float* __restrict__ x, const float* __restrict__ W,
          const float* __restrict__ Wres, const float* __restrict__ bres,
          float* __restrict__ out_p, int n) {
    constexpr int NSEG = (CONV == 1) ? 27 : 28;
    constexpr int CIN = (CONV == 1) ? 32 : 64;
    extern __shared__ __align__(16) float sm[];
    float* As = sm;                  // [CIN][128]
    float* Ws = sm + CIN * 128;      // 2 x [CIN][64]
    const uint32_t WsA = smem_u32(Ws);

    const int tid = threadIdx.x;
    const long long b = blockIdx.x;
    const long long base = b * 512;
    const float* feat = (CONV == 1) ? g_h1 : g_h2;
    float* o = (CONV == 1) ? g_h2 : out_p;
    const int vg = tid >> 3, cg = tid & 7;
    const int gslot = tid >> 1, gpart = tid & 1;

    auto seg_of = [](int i) -> int { return (i == 0) ? 13 : (i <= 13 ? i - 1 : i); };

    // prefetch W for first seg (13)
    for (int i = tid * 16; i < CIN * 64 * 4; i += 4096)
        CP16(WsA + i, (const char*)(W + 13 * CIN * 64) + i);
    CP_COMMIT();

    for (int si = 0; si < NSEG; ++si) {
        const int seg = seg_of(si);
        CP_WAIT0();
        __syncthreads();
        if (si + 1 < NSEG) {
            const int nseg = seg_of(si + 1);
            const bool nres = (CONV == 2 && nseg == 27);
            const float* src = nres ? Wres : (W + nseg * CIN * 64);
            const int nbytes = nres ? 32 * 64 * 4 : CIN * 64 * 4;
            const uint32_t dA = WsA + ((si + 1) & 1) * CIN * 64 * 4;
            for (int i = tid * 16; i < nbytes; i += 4096) CP16(dA + i, (const char*)src + i);
            CP_COMMIT();
        }
        const bool resid = (CONV == 2 && seg == 27);
        const int cin = resid ? 32 : CIN;
        const int cnt = resid ? (int)((base + 512 <= n) ? 512 : (n - base))
                              : g_cnt[b * 27 + seg];
        const int npass = (cnt + 127) >> 7;
        const int* eb = g_ent + ((long long)b * 27 + (seg < 27 ? seg : 0)) * 512;
        const float4* gfeat = (const float4*)(resid ? x : feat);
        const int rowf4 = resid ? 8 : (CIN / 4);
        const int f4pt = cin / 8;  // float4s per gather thread
        const bool store_mode = (si == 0);
        const float* Wb = Ws + (si & 1) * CIN * 64;

        for (int p = 0; p < npass; ++p) {
            __syncthreads();  // prior pass fully done before As reuse
            {   // gather 128 entries, transposed
                int e = p * 128 + gslot;
                int src_i = -1;
                if (e < cnt) src_i = resid ? (int)(base + e) : (eb[e] & 0xFFFFF);
                if (src_i >= 0) {
                    const float4* fr = gfeat + (long long)src_i * rowf4;
#pragma unroll
                    for (int j = 0; j < f4pt; ++j) {
                        int f4i = gpart * f4pt + j;
                        float4 t = fr[f4i];
                        As[(f4i * 4 + 0) * 128 + gslot] = t.x;
                        As[(f4i * 4 + 1) * 128 + gslot] = t.y;
                        As[(f4i * 4 + 2) * 128 + gslot] = t.z;
                        As[(f4i * 4 + 3) * 128 + gslot] = t.w;
                    }
                } else {
#pragma unroll
                    for (int j = 0; j < f4pt; ++j) {
                        int f4i = gpart * f4pt + j;
                        As[(f4i * 4 + 0) * 128 + gslot] = 0.f;
                        As[(f4i * 4 + 1) * 128 + gslot] = 0.f;
                        As[(f4i * 4 + 2) * 128 + gslot] = 0.f;
                        As[(f4i * 4 + 3) * 128 + gslot] = 0.f;
                    }
                }
            }
            __syncthreads();
            // compute 4 vox x 8 ch (f32x2)
            u64 acc[4][4];
#pragma unroll
            for (int a = 0; a < 4; ++a)
#pragma unroll
                for (int q = 0; q < 4; ++q) acc[a][q] = 0ull;
#pragma unroll 8
            for (int c = 0; c < cin; ++c) {
                float4 av = *(const float4*)&As[c * 128 + (vg << 2)];
                const u64* wr = (const u64*)(Wb + c * 64);
                u64 w0 = wr[cg], w1 = wr[cg + 8], w2 = wr[cg + 16], w3 = wr[cg + 24];
                u64 a0 = pack2(av.x, av.x), a1 = pack2(av.y, av.y);
                u64 a2 = pack2(av.z, av.z), a3 = pack2(av.w, av.w);
                ffma2(acc[0][0], a0, w0); ffma2(acc[0][1], a0, w1);
                ffma2(acc[0][2], a0, w2); ffma2(acc[0][3], a0, w3);
                ffma2(acc[1][0], a1, w0); ffma2(acc[1][1], a1, w1);
                ffma2(acc[1][2], a1, w2); ffma2(acc[1][3], a1, w3);
                ffma2(acc[2][0], a2, w0); ffma2(acc[2][1], a2, w1);
                ffma2(acc[2][2], a2, w2); ffma2(acc[2][3], a2, w3);
                ffma2(acc[3][0], a3, w0); ffma2(acc[3][1], a3, w1);
                ffma2(acc[3][2], a3, w2); ffma2(acc[3][3], a3, w3);
            }
            // scatter (no races: each lv appears once per segment; segs sync-separated)
#pragma unroll
            for (int vv = 0; vv < 4; ++vv) {
                int e = p * 128 + (vg << 2) + vv;
                if (e >= cnt) continue;
                int lv = resid ? e : (eb[e] >> 20);
                float* op = o + (base + lv) * 64;
#pragma unroll
                for (int q = 0; q < 4; ++q) {
                    float lo, hi;
                    unpack2(acc[vv][q], lo, hi);
                    int c0 = 2 * cg + 16 * q;
                    if (store_mode) {
                        if (CONV == 2) { lo += bres[c0]; hi += bres[c0 + 1]; }
                        *(float2*)(op + c0) = make_float2(lo, hi);
                    } else {
                        float2 v = *(const float2*)(op + c0);
                        *(float2*)(op + c0) = make_float2(v.x + lo, v.y + hi);
                    }
                }
            }
        }
    }
}

// ---------------- launch ----------------
extern "C" void kernel_launch(void* const* d_in, const int* in_sizes, int n_in,
                              void* d_out, int out_size) {
    const float* x = (const float*)d_in[0];
    const int* nbr = (const int*)d_in[1];
    const float* W1 = (const float*)d_in[2];
    const float* W2 = (const float*)d_in[3];
    const float* Wres = (const float*)d_in[4];
    const float* bres = (const float*)d_in[5];
    const float* g1 = (const float*)d_in[6];
    const float* b1 = (const float*)d_in[7];
    const float* g2 = (const float*)d_in[8];
    const float* b2 = (const float*)d_in[9];
    float* out = (float*)d_out;

    const int n = NVOX;
    const float invn = 1.0f / (float)n;
    const int SM1 = (32 * 128 + 2 * 32 * 64) * 4;  // 32 KB
    const int SM2 = (64 * 128 + 2 * 64 * 64) * 4;  // 64 KB

    cudaFuncSetAttribute(conv_pass<1>, cudaFuncAttributeMaxDynamicSharedMemorySize, SM1);
    cudaFuncSetAttribute(conv_pass<2>, cudaFuncAttributeMaxDynamicSharedMemorySize, SM2);

    prep_compact<<<NBLK, 512>>>(nbr, n);
    bn_stats_kernel<32><<<NB_STATS, 256>>>(x, n);
    bn_final256<32><<<1, 256>>>(g1, b1, invn);
    bn_apply1<<<2048, 256>>>(x, n);
    conv_pass<1><<<NBLK, 256, SM1>>>(x, W1, Wres, bres, nullptr, n);
    bn_stats_kernel<64><<<NB_STATS, 256>>>(nullptr, n);
    bn_final256<64><<<1, 256>>>(g2, b2, invn);
    bn_apply2<<<2048, 256>>>(n);
    conv_pass<2><<<NBLK, 256, SM2>>>(x, W2, Wres, bres, out, n);
}